// round 3
// baseline (speedup 1.0000x reference)
#include <cuda_runtime.h>
#include <cuda_bf16.h>
#include <cstdint>

#define HH 768
#define WW 768
#define HW (768*768)
#define IP 769                 // integral image pitch (769x769 per channel)
#define IPP (769*769)

// ---------------- scratch (device globals: allocation-free) ----------------
__device__ float g_feat1[32u * HW];           // conv1 output (75.5 MB)
__device__ float g_integ[64u * IPP];          // conv2 output + integral image (151 MB, fp32)

// ---------------- f32x2 packed-FMA helpers (sm_103a) ----------------
__device__ __forceinline__ unsigned long long pk2(float lo, float hi) {
    unsigned long long r;
    asm("mov.b64 %0, {%1, %2};" : "=l"(r) : "r"(__float_as_uint(lo)), "r"(__float_as_uint(hi)));
    return r;
}
__device__ __forceinline__ void upk2(unsigned long long d, float& lo, float& hi) {
    unsigned int a, b;
    asm("mov.b64 {%0, %1}, %2;" : "=r"(a), "=r"(b) : "l"(d));
    lo = __uint_as_float(a); hi = __uint_as_float(b);
}
__device__ __forceinline__ unsigned long long ffma2(unsigned long long a, unsigned long long b,
                                                    unsigned long long c) {
    unsigned long long d;
    asm("fma.rn.f32x2 %0, %1, %2, %3;" : "=l"(d) : "l"(a), "l"(b), "l"(c));
    return d;
}

// ---------------- conv1: 3->32, 3x3, pad 1, fused bias+relu+bn1 ----------------
__global__ __launch_bounds__(256) void conv1_k(
    const float* __restrict__ img, const float* __restrict__ w,
    const float* __restrict__ bias, const float* __restrict__ gg,
    const float* __restrict__ bb, const float* __restrict__ mm,
    const float* __restrict__ vv)
{
    __shared__ __align__(16) float s_in[3][18][18];
    __shared__ __align__(16) float s_w[27 * 32];
    __shared__ float s_scale[32], s_shift[32], s_bias[32];

    const int tx = threadIdx.x, ty = threadIdx.y;
    const int tid = ty * 16 + tx;

    for (int i = tid; i < 864; i += 256) {
        int o = i / 27, r = i % 27;
        s_w[r * 32 + o] = w[i];
    }
    if (tid < 32) {
        float sc = gg[tid] * rsqrtf(vv[tid] + 1e-5f);
        s_scale[tid] = sc;
        s_shift[tid] = bb[tid] - mm[tid] * sc;
        s_bias[tid]  = bias[tid];
    }
    const int bx0 = blockIdx.x * 16 - 1, by0 = blockIdx.y * 16 - 1;
    for (int i = tid; i < 3 * 324; i += 256) {
        int c = i / 324, r = i % 324, yy = r / 18, xx = r % 18;
        int gy = by0 + yy, gx = bx0 + xx;
        float val = (gy >= 0 && gy < HH && gx >= 0 && gx < WW)
                        ? img[c * HW + gy * WW + gx] : 0.f;
        s_in[c][yy][xx] = val;
    }
    __syncthreads();

    float acc[32];
    #pragma unroll
    for (int o = 0; o < 32; o++) acc[o] = s_bias[o];

    #pragma unroll 1
    for (int c = 0; c < 3; c++) {
        #pragma unroll
        for (int t = 0; t < 9; t++) {
            float vr = s_in[c][ty + t / 3][tx + t % 3];
            const float4* wp = (const float4*)&s_w[(c * 9 + t) * 32];
            #pragma unroll
            for (int q = 0; q < 8; q++) {
                float4 ww = wp[q];
                acc[4*q+0] = fmaf(vr, ww.x, acc[4*q+0]);
                acc[4*q+1] = fmaf(vr, ww.y, acc[4*q+1]);
                acc[4*q+2] = fmaf(vr, ww.z, acc[4*q+2]);
                acc[4*q+3] = fmaf(vr, ww.w, acc[4*q+3]);
            }
        }
    }

    const int y = blockIdx.y * 16 + ty, x = blockIdx.x * 16 + tx;
    #pragma unroll
    for (int o = 0; o < 32; o++) {
        float r = fmaxf(acc[o], 0.f) * s_scale[o] + s_shift[o];
        g_feat1[(size_t)o * HW + y * WW + x] = r;
    }
}

// ---------------- conv2: 32->64, 3x3, pad 1, fused bias+relu+bn2 ----------------
// Each thread computes 2 adjacent x-pixels for all 64 output channels.
// Tile: 32 wide x 16 tall. Writes fp32 (scalar stores — IP is odd, so
// consecutive-element addresses are only 4-byte aligned) into g_integ
// interior at [c][y+1][x+1].
__global__ __launch_bounds__(256) void conv2_k(
    const float* __restrict__ w, const float* __restrict__ bias,
    const float* __restrict__ gg, const float* __restrict__ bb,
    const float* __restrict__ mm, const float* __restrict__ vv)
{
    __shared__ __align__(16) float s_in[8][18][34];
    __shared__ __align__(16) float s_w[8 * 9 * 64];
    __shared__ float s_scale[64], s_shift[64];

    const int tx = threadIdx.x, ty = threadIdx.y;
    const int tid = ty * 16 + tx;

    if (tid < 64) {
        float sc = gg[tid] * rsqrtf(vv[tid] + 1e-5f);
        s_scale[tid] = sc;
        s_shift[tid] = bb[tid] - mm[tid] * sc;
    }

    unsigned long long accA[32], accB[32];
    #pragma unroll
    for (int k = 0; k < 32; k++) {
        accA[k] = pk2(bias[2*k], bias[2*k+1]);
        accB[k] = accA[k];
    }

    const int bx0 = blockIdx.x * 32 - 1, by0 = blockIdx.y * 16 - 1;

    #pragma unroll 1
    for (int cc = 0; cc < 4; cc++) {
        __syncthreads();
        // input chunk: channels [cc*8, cc*8+8), 18 rows x 34 cols halo tile
        for (int i = tid; i < 8 * 18 * 34; i += 256) {
            int ci = i / (18*34), r = i % (18*34), yy = r / 34, xx = r % 34;
            int gy = by0 + yy, gx = bx0 + xx;
            float val = (gy >= 0 && gy < HH && gx >= 0 && gx < WW)
                            ? g_feat1[(size_t)(cc * 8 + ci) * HW + gy * WW + gx] : 0.f;
            s_in[ci][yy][xx] = val;
        }
        // weight chunk: w[o][ic][t] flat = o*288 + cc*72 + r, r = ci*9+t -> s_w[r*64+o]
        for (int i = tid; i < 4608; i += 256) {
            int r = i >> 6, o = i & 63;
            s_w[i] = w[o * 288 + cc * 72 + r];
        }
        __syncthreads();

        #pragma unroll 1
        for (int ci = 0; ci < 8; ci++) {
            // both pixels need rows ty..ty+2, cols 2tx .. 2tx+3
            float vin[3][4];
            #pragma unroll
            for (int r = 0; r < 3; r++)
                #pragma unroll
                for (int c4 = 0; c4 < 4; c4++)
                    vin[r][c4] = s_in[ci][ty + r][2 * tx + c4];
            #pragma unroll
            for (int t = 0; t < 9; t++) {
                int r = t / 3, cq = t % 3;
                unsigned long long v2a = pk2(vin[r][cq],     vin[r][cq]);
                unsigned long long v2b = pk2(vin[r][cq + 1], vin[r][cq + 1]);
                const ulonglong2* wp = (const ulonglong2*)&s_w[(ci * 9 + t) * 64];
                #pragma unroll
                for (int k2 = 0; k2 < 16; k2++) {
                    ulonglong2 q = wp[k2];
                    accA[2*k2+0] = ffma2(v2a, q.x, accA[2*k2+0]);
                    accA[2*k2+1] = ffma2(v2a, q.y, accA[2*k2+1]);
                    accB[2*k2+0] = ffma2(v2b, q.x, accB[2*k2+0]);
                    accB[2*k2+1] = ffma2(v2b, q.y, accB[2*k2+1]);
                }
            }
        }
    }

    const int y = blockIdx.y * 16 + ty, x0 = blockIdx.x * 32 + 2 * tx;
    const size_t base = (size_t)(y + 1) * IP + (x0 + 1);
    #pragma unroll
    for (int k = 0; k < 32; k++) {
        float a0, a1, b0, b1;
        upk2(accA[k], a0, a1);
        upk2(accB[k], b0, b1);
        float* p0 = &g_integ[(size_t)(2*k)   * IPP + base];
        float* p1 = &g_integ[(size_t)(2*k+1) * IPP + base];
        p0[0] = fmaxf(a0, 0.f) * s_scale[2*k]   + s_shift[2*k];
        p0[1] = fmaxf(b0, 0.f) * s_scale[2*k]   + s_shift[2*k];
        p1[0] = fmaxf(a1, 0.f) * s_scale[2*k+1] + s_shift[2*k+1];
        p1[1] = fmaxf(b1, 0.f) * s_scale[2*k+1] + s_shift[2*k+1];
    }
}

// ---------------- zero integral-image borders ----------------
__global__ void zborder_k() {
    int i = blockIdx.x * 256 + threadIdx.x;
    if (i >= 64 * IP * 2) return;
    if (i < 64 * IP) {
        int c = i / IP, k = i % IP;
        g_integ[(size_t)c * IPP + k] = 0.f;              // row 0
    } else {
        i -= 64 * IP;
        int c = i / IP, k = i % IP;
        g_integ[(size_t)c * IPP + (size_t)k * IP] = 0.f; // col 0
    }
}

// ---------------- row-wise inclusive scan (x direction), fp32 ----------------
__global__ __launch_bounds__(256) void rowscan_k() {
    const int warp = threadIdx.x >> 5, lane = threadIdx.x & 31;
    const int row = blockIdx.x * 8 + warp;      // 0 .. 64*768-1
    const int c = row / HH, y = row % HH + 1;
    float* p = g_integ + (size_t)c * IPP + (size_t)y * IP + 1;

    float v[24];
    #pragma unroll
    for (int i = 0; i < 24; i++) v[i] = p[lane * 24 + i];
    #pragma unroll
    for (int i = 1; i < 24; i++) v[i] += v[i - 1];
    float sc = v[23];
    #pragma unroll
    for (int d = 1; d < 32; d <<= 1) {
        float n = __shfl_up_sync(0xffffffffu, sc, d);
        if (lane >= d) sc += n;
    }
    float excl = __shfl_up_sync(0xffffffffu, sc, 1);
    if (lane == 0) excl = 0.f;
    #pragma unroll
    for (int i = 0; i < 24; i++) p[lane * 24 + i] = v[i] + excl;
}

// ---------------- column-wise inclusive scan (y direction), fp32 ----------------
__global__ __launch_bounds__(256) void colscan_k() {
    int idx = blockIdx.x * 256 + threadIdx.x;
    if (idx >= 64 * WW) return;
    int c = idx / WW, x = idx % WW + 1;
    float* p = g_integ + (size_t)c * IPP + x;
    float s = 0.f;
    #pragma unroll 4
    for (int y = 1; y <= HH; y++) {
        s += p[(size_t)y * IP];
        p[(size_t)y * IP] = s;
    }
}

// ---------------- ROI pool (5x5 via integral image) + FC1(relu) + FC2 ----------------
__global__ __launch_bounds__(128) void roi_fc_k(
    const int* __restrict__ boxes,
    const float* __restrict__ fc1w, const float* __restrict__ fc1b,
    const float* __restrict__ fc2w, const float* __restrict__ fc2b,
    float* __restrict__ out)
{
    __shared__ float s_pool[1600];
    __shared__ float s_h1[128];
    __shared__ int sy0[5], sy1[5], sx0[5], sx1[5];

    const int b = blockIdx.x, tid = threadIdx.x;
    if (tid < 5) {
        int xmin = boxes[b*4+0], ymin = boxes[b*4+1];
        int xmax = boxes[b*4+2], ymax = boxes[b*4+3];
        int bh = ymax - ymin, bw = xmax - xmin;
        sy0[tid] = ymin + tid * bh / 5;
        sy1[tid] = ymin + ((tid + 1) * bh + 4) / 5;
        sx0[tid] = xmin + tid * bw / 5;
        sx1[tid] = xmin + ((tid + 1) * bw + 4) / 5;
    }
    __syncthreads();

    for (int idx = tid; idx < 1600; idx += 128) {
        int c = idx / 25, r = idx % 25, i = r / 5, j = r % 5;
        const float* I = g_integ + (size_t)c * IPP;
        double s = (double)I[(size_t)sy1[i] * IP + sx1[j]] - (double)I[(size_t)sy0[i] * IP + sx1[j]]
                 - (double)I[(size_t)sy1[i] * IP + sx0[j]] + (double)I[(size_t)sy0[i] * IP + sx0[j]];
        double area = (double)((sy1[i] - sy0[i]) * (sx1[j] - sx0[j]));
        s_pool[idx] = (float)(s / area);
    }
    __syncthreads();

    const int warp = tid >> 5, lane = tid & 31;
    for (int o = warp; o < 128; o += 4) {
        const float* wr = fc1w + o * 1600;
        float sum = 0.f;
        for (int k = lane; k < 1600; k += 32) sum = fmaf(wr[k], s_pool[k], sum);
        #pragma unroll
        for (int d = 16; d; d >>= 1) sum += __shfl_down_sync(0xffffffffu, sum, d);
        if (lane == 0) s_h1[o] = fmaxf(sum + fc1b[o], 0.f);
    }
    __syncthreads();

    {
        int o = warp;
        float sum = 0.f;
        #pragma unroll
        for (int k = lane; k < 128; k += 32) sum = fmaf(fc2w[o * 128 + k], s_h1[k], sum);
        #pragma unroll
        for (int d = 16; d; d >>= 1) sum += __shfl_down_sync(0xffffffffu, sum, d);
        if (lane == 0) out[b * 4 + o] = sum + fc2b[o];
    }
}

// ---------------- launch ----------------
extern "C" void kernel_launch(void* const* d_in, const int* in_sizes, int n_in,
                              void* d_out, int out_size)
{
    const float* image = (const float*)d_in[0];
    const int*   boxes = (const int*)  d_in[1];
    const float* c1w = (const float*)d_in[2];
    const float* c1b = (const float*)d_in[3];
    const float* b1g = (const float*)d_in[4];
    const float* b1b = (const float*)d_in[5];
    const float* b1m = (const float*)d_in[6];
    const float* b1v = (const float*)d_in[7];
    const float* c2w = (const float*)d_in[8];
    const float* c2b = (const float*)d_in[9];
    const float* b2g = (const float*)d_in[10];
    const float* b2b = (const float*)d_in[11];
    const float* b2m = (const float*)d_in[12];
    const float* b2v = (const float*)d_in[13];
    const float* f1w = (const float*)d_in[14];
    const float* f1b = (const float*)d_in[15];
    const float* f2w = (const float*)d_in[16];
    const float* f2b = (const float*)d_in[17];
    float* out = (float*)d_out;

    conv1_k<<<dim3(48, 48), dim3(16, 16)>>>(image, c1w, c1b, b1g, b1b, b1m, b1v);
    zborder_k<<<(64 * IP * 2 + 255) / 256, 256>>>();
    conv2_k<<<dim3(24, 48), dim3(16, 16)>>>(c2w, c2b, b2g, b2b, b2m, b2v);
    rowscan_k<<<64 * HH / 8, 256>>>();
    colscan_k<<<(64 * WW + 255) / 256, 256>>>();
    roi_fc_k<<<512, 128>>>(boxes, f1w, f1b, f2w, f2b, out);
}

// round 4
// speedup vs baseline: 1.7997x; 1.7997x over previous
#include <cuda_runtime.h>
#include <cuda_bf16.h>
#include <cstdint>

#define HH 768
#define WW 768
#define HW (768*768)
#define IP 769                 // integral image pitch (769x769 per channel)
#define IPP (769*769)

// ---------------- scratch (device globals: allocation-free) ----------------
__device__ float g_feat1[32u * HW];           // conv1 output (75.5 MB)
__device__ float g_integ[64u * IPP];          // conv2 output + integral image (151 MB, fp32)

// ---------------- f32x2 packed-FMA helpers (sm_103a) ----------------
__device__ __forceinline__ unsigned long long pk2(float lo, float hi) {
    unsigned long long r;
    asm("mov.b64 %0, {%1, %2};" : "=l"(r) : "r"(__float_as_uint(lo)), "r"(__float_as_uint(hi)));
    return r;
}
__device__ __forceinline__ void upk2(unsigned long long d, float& lo, float& hi) {
    unsigned int a, b;
    asm("mov.b64 {%0, %1}, %2;" : "=r"(a), "=r"(b) : "l"(d));
    lo = __uint_as_float(a); hi = __uint_as_float(b);
}
__device__ __forceinline__ unsigned long long ffma2(unsigned long long a, unsigned long long b,
                                                    unsigned long long c) {
    unsigned long long d;
    asm("fma.rn.f32x2 %0, %1, %2, %3;" : "=l"(d) : "l"(a), "l"(b), "l"(c));
    return d;
}

// ---------------- conv1: 3->32, 3x3, pad 1, fused bias+relu+bn1 ----------------
__global__ __launch_bounds__(256) void conv1_k(
    const float* __restrict__ img, const float* __restrict__ w,
    const float* __restrict__ bias, const float* __restrict__ gg,
    const float* __restrict__ bb, const float* __restrict__ mm,
    const float* __restrict__ vv)
{
    __shared__ __align__(16) float s_in[3][18][18];
    __shared__ __align__(16) float s_w[27 * 32];
    __shared__ float s_scale[32], s_shift[32], s_bias[32];

    const int tx = threadIdx.x, ty = threadIdx.y;
    const int tid = ty * 16 + tx;

    for (int i = tid; i < 864; i += 256) {
        int o = i / 27, r = i % 27;
        s_w[r * 32 + o] = w[i];
    }
    if (tid < 32) {
        float sc = gg[tid] * rsqrtf(vv[tid] + 1e-5f);
        s_scale[tid] = sc;
        s_shift[tid] = bb[tid] - mm[tid] * sc;
        s_bias[tid]  = bias[tid];
    }
    const int bx0 = blockIdx.x * 16 - 1, by0 = blockIdx.y * 16 - 1;
    for (int i = tid; i < 3 * 324; i += 256) {
        int c = i / 324, r = i % 324, yy = r / 18, xx = r % 18;
        int gy = by0 + yy, gx = bx0 + xx;
        float val = (gy >= 0 && gy < HH && gx >= 0 && gx < WW)
                        ? img[c * HW + gy * WW + gx] : 0.f;
        s_in[c][yy][xx] = val;
    }
    __syncthreads();

    float acc[32];
    #pragma unroll
    for (int o = 0; o < 32; o++) acc[o] = s_bias[o];

    #pragma unroll 1
    for (int c = 0; c < 3; c++) {
        #pragma unroll
        for (int t = 0; t < 9; t++) {
            float vr = s_in[c][ty + t / 3][tx + t % 3];
            const float4* wp = (const float4*)&s_w[(c * 9 + t) * 32];
            #pragma unroll
            for (int q = 0; q < 8; q++) {
                float4 ww = wp[q];
                acc[4*q+0] = fmaf(vr, ww.x, acc[4*q+0]);
                acc[4*q+1] = fmaf(vr, ww.y, acc[4*q+1]);
                acc[4*q+2] = fmaf(vr, ww.z, acc[4*q+2]);
                acc[4*q+3] = fmaf(vr, ww.w, acc[4*q+3]);
            }
        }
    }

    const int y = blockIdx.y * 16 + ty, x = blockIdx.x * 16 + tx;
    #pragma unroll
    for (int o = 0; o < 32; o++) {
        float r = fmaxf(acc[o], 0.f) * s_scale[o] + s_shift[o];
        g_feat1[(size_t)o * HW + y * WW + x] = r;
    }
}

// ---------------- conv2: 32->64, 3x3, pad 1, fused bias+relu+bn2 ----------------
// Each thread computes 2 adjacent x-pixels for all 64 output channels.
// Scalar stores (IP odd -> only 4B alignment guaranteed).
__global__ __launch_bounds__(256) void conv2_k(
    const float* __restrict__ w, const float* __restrict__ bias,
    const float* __restrict__ gg, const float* __restrict__ bb,
    const float* __restrict__ mm, const float* __restrict__ vv)
{
    __shared__ __align__(16) float s_in[8][18][34];
    __shared__ __align__(16) float s_w[8 * 9 * 64];
    __shared__ float s_scale[64], s_shift[64];

    const int tx = threadIdx.x, ty = threadIdx.y;
    const int tid = ty * 16 + tx;

    if (tid < 64) {
        float sc = gg[tid] * rsqrtf(vv[tid] + 1e-5f);
        s_scale[tid] = sc;
        s_shift[tid] = bb[tid] - mm[tid] * sc;
    }

    unsigned long long accA[32], accB[32];
    #pragma unroll
    for (int k = 0; k < 32; k++) {
        accA[k] = pk2(bias[2*k], bias[2*k+1]);
        accB[k] = accA[k];
    }

    const int bx0 = blockIdx.x * 32 - 1, by0 = blockIdx.y * 16 - 1;

    #pragma unroll 1
    for (int cc = 0; cc < 4; cc++) {
        __syncthreads();
        for (int i = tid; i < 8 * 18 * 34; i += 256) {
            int ci = i / (18*34), r = i % (18*34), yy = r / 34, xx = r % 34;
            int gy = by0 + yy, gx = bx0 + xx;
            float val = (gy >= 0 && gy < HH && gx >= 0 && gx < WW)
                            ? g_feat1[(size_t)(cc * 8 + ci) * HW + gy * WW + gx] : 0.f;
            s_in[ci][yy][xx] = val;
        }
        for (int i = tid; i < 4608; i += 256) {
            int r = i >> 6, o = i & 63;
            s_w[i] = w[o * 288 + cc * 72 + r];
        }
        __syncthreads();

        #pragma unroll 1
        for (int ci = 0; ci < 8; ci++) {
            float vin[3][4];
            #pragma unroll
            for (int r = 0; r < 3; r++)
                #pragma unroll
                for (int c4 = 0; c4 < 4; c4++)
                    vin[r][c4] = s_in[ci][ty + r][2 * tx + c4];
            #pragma unroll
            for (int t = 0; t < 9; t++) {
                int r = t / 3, cq = t % 3;
                unsigned long long v2a = pk2(vin[r][cq],     vin[r][cq]);
                unsigned long long v2b = pk2(vin[r][cq + 1], vin[r][cq + 1]);
                const ulonglong2* wp = (const ulonglong2*)&s_w[(ci * 9 + t) * 64];
                #pragma unroll
                for (int k2 = 0; k2 < 16; k2++) {
                    ulonglong2 q = wp[k2];
                    accA[2*k2+0] = ffma2(v2a, q.x, accA[2*k2+0]);
                    accA[2*k2+1] = ffma2(v2a, q.y, accA[2*k2+1]);
                    accB[2*k2+0] = ffma2(v2b, q.x, accB[2*k2+0]);
                    accB[2*k2+1] = ffma2(v2b, q.y, accB[2*k2+1]);
                }
            }
        }
    }

    const int y = blockIdx.y * 16 + ty, x0 = blockIdx.x * 32 + 2 * tx;
    const size_t base = (size_t)(y + 1) * IP + (x0 + 1);
    #pragma unroll
    for (int k = 0; k < 32; k++) {
        float a0, a1, b0, b1;
        upk2(accA[k], a0, a1);
        upk2(accB[k], b0, b1);
        float* p0 = &g_integ[(size_t)(2*k)   * IPP + base];
        float* p1 = &g_integ[(size_t)(2*k+1) * IPP + base];
        p0[0] = fmaxf(a0, 0.f) * s_scale[2*k]   + s_shift[2*k];
        p0[1] = fmaxf(b0, 0.f) * s_scale[2*k]   + s_shift[2*k];
        p1[0] = fmaxf(a1, 0.f) * s_scale[2*k+1] + s_shift[2*k+1];
        p1[1] = fmaxf(b1, 0.f) * s_scale[2*k+1] + s_shift[2*k+1];
    }
}

// ---------------- zero integral-image borders ----------------
__global__ void zborder_k() {
    int i = blockIdx.x * 256 + threadIdx.x;
    if (i >= 64 * IP * 2) return;
    if (i < 64 * IP) {
        int c = i / IP, k = i % IP;
        g_integ[(size_t)c * IPP + k] = 0.f;              // row 0
    } else {
        i -= 64 * IP;
        int c = i / IP, k = i % IP;
        g_integ[(size_t)c * IPP + (size_t)k * IP] = 0.f; // col 0
    }
}

// ---------------- row-wise inclusive scan (x), fp32, COALESCED ----------------
// One warp per row. Interleaved ownership: v[i] = p[i*32 + lane] so every
// load/store instruction is a contiguous 128B transaction. Scan = 24 serial
// steps of (warp Kogge-Stone + carry broadcast).
__global__ __launch_bounds__(256) void rowscan_k() {
    const int warp = threadIdx.x >> 5, lane = threadIdx.x & 31;
    const int row = blockIdx.x * 8 + warp;      // 0 .. 64*768-1
    const int c = row / HH, y = row % HH + 1;
    float* p = g_integ + (size_t)c * IPP + (size_t)y * IP + 1;

    float v[24];
    #pragma unroll
    for (int i = 0; i < 24; i++) v[i] = p[i * 32 + lane];

    float carry = 0.f;
    #pragma unroll
    for (int i = 0; i < 24; i++) {
        float x = v[i];
        #pragma unroll
        for (int d = 1; d < 32; d <<= 1) {
            float n = __shfl_up_sync(0xffffffffu, x, d);
            if (lane >= d) x += n;
        }
        x += carry;
        carry = __shfl_sync(0xffffffffu, x, 31);
        v[i] = x;
    }

    #pragma unroll
    for (int i = 0; i < 24; i++) p[i * 32 + lane] = v[i];
}

// ---------------- column-wise inclusive scan (y direction), fp32 ----------------
__global__ __launch_bounds__(256) void colscan_k() {
    int idx = blockIdx.x * 256 + threadIdx.x;
    if (idx >= 64 * WW) return;
    int c = idx / WW, x = idx % WW + 1;
    float* p = g_integ + (size_t)c * IPP + x;
    float s = 0.f;
    #pragma unroll 8
    for (int y = 1; y <= HH; y++) {
        s += p[(size_t)y * IP];
        p[(size_t)y * IP] = s;
    }
}

// ---------------- ROI pool (5x5 via integral image) + FC1(relu) + FC2 ----------------
__global__ __launch_bounds__(128) void roi_fc_k(
    const int* __restrict__ boxes,
    const float* __restrict__ fc1w, const float* __restrict__ fc1b,
    const float* __restrict__ fc2w, const float* __restrict__ fc2b,
    float* __restrict__ out)
{
    __shared__ float s_pool[1600];
    __shared__ float s_h1[128];
    __shared__ int sy0[5], sy1[5], sx0[5], sx1[5];

    const int b = blockIdx.x, tid = threadIdx.x;
    if (tid < 5) {
        int xmin = boxes[b*4+0], ymin = boxes[b*4+1];
        int xmax = boxes[b*4+2], ymax = boxes[b*4+3];
        int bh = ymax - ymin, bw = xmax - xmin;
        sy0[tid] = ymin + tid * bh / 5;
        sy1[tid] = ymin + ((tid + 1) * bh + 4) / 5;
        sx0[tid] = xmin + tid * bw / 5;
        sx1[tid] = xmin + ((tid + 1) * bw + 4) / 5;
    }
    __syncthreads();

    for (int idx = tid; idx < 1600; idx += 128) {
        int c = idx / 25, r = idx % 25, i = r / 5, j = r % 5;
        const float* I = g_integ + (size_t)c * IPP;
        double s = (double)I[(size_t)sy1[i] * IP + sx1[j]] - (double)I[(size_t)sy0[i] * IP + sx1[j]]
                 - (double)I[(size_t)sy1[i] * IP + sx0[j]] + (double)I[(size_t)sy0[i] * IP + sx0[j]];
        double area = (double)((sy1[i] - sy0[i]) * (sx1[j] - sx0[j]));
        s_pool[idx] = (float)(s / area);
    }
    __syncthreads();

    const int warp = tid >> 5, lane = tid & 31;
    for (int o = warp; o < 128; o += 4) {
        const float* wr = fc1w + o * 1600;
        float sum = 0.f;
        for (int k = lane; k < 1600; k += 32) sum = fmaf(wr[k], s_pool[k], sum);
        #pragma unroll
        for (int d = 16; d; d >>= 1) sum += __shfl_down_sync(0xffffffffu, sum, d);
        if (lane == 0) s_h1[o] = fmaxf(sum + fc1b[o], 0.f);
    }
    __syncthreads();

    {
        int o = warp;
        float sum = 0.f;
        #pragma unroll
        for (int k = lane; k < 128; k += 32) sum = fmaf(fc2w[o * 128 + k], s_h1[k], sum);
        #pragma unroll
        for (int d = 16; d; d >>= 1) sum += __shfl_down_sync(0xffffffffu, sum, d);
        if (lane == 0) out[b * 4 + o] = sum + fc2b[o];
    }
}

// ---------------- launch ----------------
extern "C" void kernel_launch(void* const* d_in, const int* in_sizes, int n_in,
                              void* d_out, int out_size)
{
    const float* image = (const float*)d_in[0];
    const int*   boxes = (const int*)  d_in[1];
    const float* c1w = (const float*)d_in[2];
    const float* c1b = (const float*)d_in[3];
    const float* b1g = (const float*)d_in[4];
    const float* b1b = (const float*)d_in[5];
    const float* b1m = (const float*)d_in[6];
    const float* b1v = (const float*)d_in[7];
    const float* c2w = (const float*)d_in[8];
    const float* c2b = (const float*)d_in[9];
    const float* b2g = (const float*)d_in[10];
    const float* b2b = (const float*)d_in[11];
    const float* b2m = (const float*)d_in[12];
    const float* b2v = (const float*)d_in[13];
    const float* f1w = (const float*)d_in[14];
    const float* f1b = (const float*)d_in[15];
    const float* f2w = (const float*)d_in[16];
    const float* f2b = (const float*)d_in[17];
    float* out = (float*)d_out;

    conv1_k<<<dim3(48, 48), dim3(16, 16)>>>(image, c1w, c1b, b1g, b1b, b1m, b1v);
    zborder_k<<<(64 * IP * 2 + 255) / 256, 256>>>();
    conv2_k<<<dim3(24, 48), dim3(16, 16)>>>(c2w, c2b, b2g, b2b, b2m, b2v);
    rowscan_k<<<64 * HH / 8, 256>>>();
    colscan_k<<<(64 * WW + 255) / 256, 256>>>();
    roi_fc_k<<<512, 128>>>(boxes, f1w, f1b, f2w, f2b, out);
}

// round 5
// speedup vs baseline: 1.9193x; 1.0664x over previous
#include <cuda_runtime.h>
#include <cuda_bf16.h>
#include <cstdint>

#define HH 768
#define WW 768
#define HW (768*768)
#define IP 769                 // integral image pitch (769x769 per channel)
#define IPP (769*769)

// ---------------- scratch (device globals: allocation-free) ----------------
__device__ float g_feat1[32u * HW];           // conv1 output (75.5 MB)
__device__ float g_integ[64u * IPP];          // conv2 output + integral image (151 MB, fp32)

// ---------------- f32x2 packed-FMA helpers (sm_103a) ----------------
__device__ __forceinline__ unsigned long long pk2(float lo, float hi) {
    unsigned long long r;
    asm("mov.b64 %0, {%1, %2};" : "=l"(r) : "r"(__float_as_uint(lo)), "r"(__float_as_uint(hi)));
    return r;
}
__device__ __forceinline__ void upk2(unsigned long long d, float& lo, float& hi) {
    unsigned int a, b;
    asm("mov.b64 {%0, %1}, %2;" : "=r"(a), "=r"(b) : "l"(d));
    lo = __uint_as_float(a); hi = __uint_as_float(b);
}
__device__ __forceinline__ unsigned long long ffma2(unsigned long long a, unsigned long long b,
                                                    unsigned long long c) {
    unsigned long long d;
    asm("fma.rn.f32x2 %0, %1, %2, %3;" : "=l"(d) : "l"(a), "l"(b), "l"(c));
    return d;
}

// ---------------- conv1: 3->32, 3x3, pad 1, fused bias+relu+bn1 ----------------
__global__ __launch_bounds__(256) void conv1_k(
    const float* __restrict__ img, const float* __restrict__ w,
    const float* __restrict__ bias, const float* __restrict__ gg,
    const float* __restrict__ bb, const float* __restrict__ mm,
    const float* __restrict__ vv)
{
    __shared__ __align__(16) float s_in[3][18][18];
    __shared__ __align__(16) float s_w[27 * 32];
    __shared__ float s_scale[32], s_shift[32], s_bias[32];

    const int tx = threadIdx.x, ty = threadIdx.y;
    const int tid = ty * 16 + tx;

    for (int i = tid; i < 864; i += 256) {
        int o = i / 27, r = i % 27;
        s_w[r * 32 + o] = w[i];
    }
    if (tid < 32) {
        float sc = gg[tid] * rsqrtf(vv[tid] + 1e-5f);
        s_scale[tid] = sc;
        s_shift[tid] = bb[tid] - mm[tid] * sc;
        s_bias[tid]  = bias[tid];
    }
    const int bx0 = blockIdx.x * 16 - 1, by0 = blockIdx.y * 16 - 1;
    for (int i = tid; i < 3 * 324; i += 256) {
        int c = i / 324, r = i % 324, yy = r / 18, xx = r % 18;
        int gy = by0 + yy, gx = bx0 + xx;
        float val = (gy >= 0 && gy < HH && gx >= 0 && gx < WW)
                        ? img[c * HW + gy * WW + gx] : 0.f;
        s_in[c][yy][xx] = val;
    }
    __syncthreads();

    float acc[32];
    #pragma unroll
    for (int o = 0; o < 32; o++) acc[o] = s_bias[o];

    #pragma unroll 1
    for (int c = 0; c < 3; c++) {
        #pragma unroll
        for (int t = 0; t < 9; t++) {
            float vr = s_in[c][ty + t / 3][tx + t % 3];
            const float4* wp = (const float4*)&s_w[(c * 9 + t) * 32];
            #pragma unroll
            for (int q = 0; q < 8; q++) {
                float4 ww = wp[q];
                acc[4*q+0] = fmaf(vr, ww.x, acc[4*q+0]);
                acc[4*q+1] = fmaf(vr, ww.y, acc[4*q+1]);
                acc[4*q+2] = fmaf(vr, ww.z, acc[4*q+2]);
                acc[4*q+3] = fmaf(vr, ww.w, acc[4*q+3]);
            }
        }
    }

    const int y = blockIdx.y * 16 + ty, x = blockIdx.x * 16 + tx;
    #pragma unroll
    for (int o = 0; o < 32; o++) {
        float r = fmaxf(acc[o], 0.f) * s_scale[o] + s_shift[o];
        g_feat1[(size_t)o * HW + y * WW + x] = r;
    }
}

// ---------------- conv2: 32->64, 3x3, pad 1, fused bias+relu+bn2 ----------------
// Channel-split: blockIdx.z selects 32 of 64 output channels. Each thread
// computes 2 adjacent x-pixels for its 32 channels. 2 blocks/SM for latency
// cover (__launch_bounds__(256,2) caps regs at 128; acc = 64 regs).
// Scalar stores (IP odd -> only 4B alignment guaranteed).
__global__ __launch_bounds__(256, 2) void conv2_k(
    const float* __restrict__ w, const float* __restrict__ bias,
    const float* __restrict__ gg, const float* __restrict__ bb,
    const float* __restrict__ mm, const float* __restrict__ vv)
{
    __shared__ __align__(16) float s_in[8][18][34];
    __shared__ __align__(16) float s_w[8 * 9 * 32];
    __shared__ float s_scale[32], s_shift[32];

    const int tx = threadIdx.x, ty = threadIdx.y;
    const int tid = ty * 16 + tx;
    const int oz = blockIdx.z * 32;            // output-channel base

    if (tid < 32) {
        int o = oz + tid;
        float sc = gg[o] * rsqrtf(vv[o] + 1e-5f);
        s_scale[tid] = sc;
        s_shift[tid] = bb[o] - mm[o] * sc;
    }

    unsigned long long accA[16], accB[16];
    #pragma unroll
    for (int k = 0; k < 16; k++) {
        accA[k] = pk2(bias[oz + 2*k], bias[oz + 2*k + 1]);
        accB[k] = accA[k];
    }

    const int bx0 = blockIdx.x * 32 - 1, by0 = blockIdx.y * 16 - 1;

    #pragma unroll 1
    for (int cc = 0; cc < 4; cc++) {
        __syncthreads();
        // input chunk: channels [cc*8, cc*8+8), 18 rows x 34 cols halo tile
        for (int i = tid; i < 8 * 18 * 34; i += 256) {
            int ci = i / (18*34), r = i % (18*34), yy = r / 34, xx = r % 34;
            int gy = by0 + yy, gx = bx0 + xx;
            float val = (gy >= 0 && gy < HH && gx >= 0 && gx < WW)
                            ? g_feat1[(size_t)(cc * 8 + ci) * HW + gy * WW + gx] : 0.f;
            s_in[ci][yy][xx] = val;
        }
        // weight chunk: s_w[r*32 + o] = w[(oz+o)*288 + cc*72 + r], r = ci*9+t
        for (int i = tid; i < 2304; i += 256) {
            int r = i >> 5, o = i & 31;
            s_w[i] = w[(size_t)(oz + o) * 288 + cc * 72 + r];
        }
        __syncthreads();

        #pragma unroll 1
        for (int ci = 0; ci < 8; ci++) {
            float vin[3][4];
            #pragma unroll
            for (int r = 0; r < 3; r++)
                #pragma unroll
                for (int c4 = 0; c4 < 4; c4++)
                    vin[r][c4] = s_in[ci][ty + r][2 * tx + c4];
            #pragma unroll
            for (int t = 0; t < 9; t++) {
                int r = t / 3, cq = t % 3;
                unsigned long long v2a = pk2(vin[r][cq],     vin[r][cq]);
                unsigned long long v2b = pk2(vin[r][cq + 1], vin[r][cq + 1]);
                const ulonglong2* wp = (const ulonglong2*)&s_w[(ci * 9 + t) * 32];
                #pragma unroll
                for (int k2 = 0; k2 < 8; k2++) {
                    ulonglong2 q = wp[k2];
                    accA[2*k2+0] = ffma2(v2a, q.x, accA[2*k2+0]);
                    accA[2*k2+1] = ffma2(v2a, q.y, accA[2*k2+1]);
                    accB[2*k2+0] = ffma2(v2b, q.x, accB[2*k2+0]);
                    accB[2*k2+1] = ffma2(v2b, q.y, accB[2*k2+1]);
                }
            }
        }
    }

    const int y = blockIdx.y * 16 + ty, x0 = blockIdx.x * 32 + 2 * tx;
    const size_t base = (size_t)(y + 1) * IP + (x0 + 1);
    #pragma unroll
    for (int k = 0; k < 16; k++) {
        float a0, a1, b0, b1;
        upk2(accA[k], a0, a1);
        upk2(accB[k], b0, b1);
        float* p0 = &g_integ[(size_t)(oz + 2*k)     * IPP + base];
        float* p1 = &g_integ[(size_t)(oz + 2*k + 1) * IPP + base];
        p0[0] = fmaxf(a0, 0.f) * s_scale[2*k]   + s_shift[2*k];
        p0[1] = fmaxf(b0, 0.f) * s_scale[2*k]   + s_shift[2*k];
        p1[0] = fmaxf(a1, 0.f) * s_scale[2*k+1] + s_shift[2*k+1];
        p1[1] = fmaxf(b1, 0.f) * s_scale[2*k+1] + s_shift[2*k+1];
    }
}

// ---------------- zero integral-image borders ----------------
__global__ void zborder_k() {
    int i = blockIdx.x * 256 + threadIdx.x;
    if (i >= 64 * IP * 2) return;
    if (i < 64 * IP) {
        int c = i / IP, k = i % IP;
        g_integ[(size_t)c * IPP + k] = 0.f;              // row 0
    } else {
        i -= 64 * IP;
        int c = i / IP, k = i % IP;
        g_integ[(size_t)c * IPP + (size_t)k * IP] = 0.f; // col 0
    }
}

// ---------------- row-wise inclusive scan (x), fp32, coalesced ----------------
__global__ __launch_bounds__(256) void rowscan_k() {
    const int warp = threadIdx.x >> 5, lane = threadIdx.x & 31;
    const int row = blockIdx.x * 8 + warp;      // 0 .. 64*768-1
    const int c = row / HH, y = row % HH + 1;
    float* p = g_integ + (size_t)c * IPP + (size_t)y * IP + 1;

    float v[24];
    #pragma unroll
    for (int i = 0; i < 24; i++) v[i] = p[i * 32 + lane];

    float carry = 0.f;
    #pragma unroll
    for (int i = 0; i < 24; i++) {
        float x = v[i];
        #pragma unroll
        for (int d = 1; d < 32; d <<= 1) {
            float n = __shfl_up_sync(0xffffffffu, x, d);
            if (lane >= d) x += n;
        }
        x += carry;
        carry = __shfl_sync(0xffffffffu, x, 31);
        v[i] = x;
    }

    #pragma unroll
    for (int i = 0; i < 24; i++) p[i * 32 + lane] = v[i];
}

// ---------------- column-wise inclusive scan (y direction), fp32 ----------------
__global__ __launch_bounds__(256) void colscan_k() {
    int idx = blockIdx.x * 256 + threadIdx.x;
    if (idx >= 64 * WW) return;
    int c = idx / WW, x = idx % WW + 1;
    float* p = g_integ + (size_t)c * IPP + x;
    float s = 0.f;
    #pragma unroll 8
    for (int y = 1; y <= HH; y++) {
        s += p[(size_t)y * IP];
        p[(size_t)y * IP] = s;
    }
}

// ---------------- ROI pool (5x5 via integral image) + FC1(relu) + FC2 ----------------
__global__ __launch_bounds__(128) void roi_fc_k(
    const int* __restrict__ boxes,
    const float* __restrict__ fc1w, const float* __restrict__ fc1b,
    const float* __restrict__ fc2w, const float* __restrict__ fc2b,
    float* __restrict__ out)
{
    __shared__ float s_pool[1600];
    __shared__ float s_h1[128];
    __shared__ int sy0[5], sy1[5], sx0[5], sx1[5];

    const int b = blockIdx.x, tid = threadIdx.x;
    if (tid < 5) {
        int xmin = boxes[b*4+0], ymin = boxes[b*4+1];
        int xmax = boxes[b*4+2], ymax = boxes[b*4+3];
        int bh = ymax - ymin, bw = xmax - xmin;
        sy0[tid] = ymin + tid * bh / 5;
        sy1[tid] = ymin + ((tid + 1) * bh + 4) / 5;
        sx0[tid] = xmin + tid * bw / 5;
        sx1[tid] = xmin + ((tid + 1) * bw + 4) / 5;
    }
    __syncthreads();

    for (int idx = tid; idx < 1600; idx += 128) {
        int c = idx / 25, r = idx % 25, i = r / 5, j = r % 5;
        const float* I = g_integ + (size_t)c * IPP;
        double s = (double)I[(size_t)sy1[i] * IP + sx1[j]] - (double)I[(size_t)sy0[i] * IP + sx1[j]]
                 - (double)I[(size_t)sy1[i] * IP + sx0[j]] + (double)I[(size_t)sy0[i] * IP + sx0[j]];
        double area = (double)((sy1[i] - sy0[i]) * (sx1[j] - sx0[j]));
        s_pool[idx] = (float)(s / area);
    }
    __syncthreads();

    const int warp = tid >> 5, lane = tid & 31;
    for (int o = warp; o < 128; o += 4) {
        const float* wr = fc1w + o * 1600;
        float sum = 0.f;
        for (int k = lane; k < 1600; k += 32) sum = fmaf(wr[k], s_pool[k], sum);
        #pragma unroll
        for (int d = 16; d; d >>= 1) sum += __shfl_down_sync(0xffffffffu, sum, d);
        if (lane == 0) s_h1[o] = fmaxf(sum + fc1b[o], 0.f);
    }
    __syncthreads();

    {
        int o = warp;
        float sum = 0.f;
        #pragma unroll
        for (int k = lane; k < 128; k += 32) sum = fmaf(fc2w[o * 128 + k], s_h1[k], sum);
        #pragma unroll
        for (int d = 16; d; d >>= 1) sum += __shfl_down_sync(0xffffffffu, sum, d);
        if (lane == 0) out[b * 4 + o] = sum + fc2b[o];
    }
}

// ---------------- launch ----------------
extern "C" void kernel_launch(void* const* d_in, const int* in_sizes, int n_in,
                              void* d_out, int out_size)
{
    const float* image = (const float*)d_in[0];
    const int*   boxes = (const int*)  d_in[1];
    const float* c1w = (const float*)d_in[2];
    const float* c1b = (const float*)d_in[3];
    const float* b1g = (const float*)d_in[4];
    const float* b1b = (const float*)d_in[5];
    const float* b1m = (const float*)d_in[6];
    const float* b1v = (const float*)d_in[7];
    const float* c2w = (const float*)d_in[8];
    const float* c2b = (const float*)d_in[9];
    const float* b2g = (const float*)d_in[10];
    const float* b2b = (const float*)d_in[11];
    const float* b2m = (const float*)d_in[12];
    const float* b2v = (const float*)d_in[13];
    const float* f1w = (const float*)d_in[14];
    const float* f1b = (const float*)d_in[15];
    const float* f2w = (const float*)d_in[16];
    const float* f2b = (const float*)d_in[17];
    float* out = (float*)d_out;

    conv1_k<<<dim3(48, 48), dim3(16, 16)>>>(image, c1w, c1b, b1g, b1b, b1m, b1v);
    zborder_k<<<(64 * IP * 2 + 255) / 256, 256>>>();
    conv2_k<<<dim3(24, 48, 2), dim3(16, 16)>>>(c2w, c2b, b2g, b2b, b2m, b2v);
    rowscan_k<<<64 * HH / 8, 256>>>();
    colscan_k<<<(64 * WW + 255) / 256, 256>>>();
    roi_fc_k<<<512, 128>>>(boxes, f1w, f1b, f2w, f2b, out);
}

// round 6
// speedup vs baseline: 1.9266x; 1.0038x over previous
#include <cuda_runtime.h>
#include <cuda_bf16.h>
#include <cstdint>

#define HH 768
#define WW 768
#define HW (768*768)
#define IP 769                 // integral image pitch (769x769 per channel)
#define IPP (769*769)

// ---------------- scratch (device globals: allocation-free) ----------------
__device__ float g_feat1[32u * HW];           // conv1 output (75.5 MB)
__device__ float g_integ[64u * IPP];          // conv2 output + integral image (151 MB, fp32)

// ---------------- f32x2 packed-FMA helpers (sm_103a) ----------------
__device__ __forceinline__ unsigned long long pk2(float lo, float hi) {
    unsigned long long r;
    asm("mov.b64 %0, {%1, %2};" : "=l"(r) : "r"(__float_as_uint(lo)), "r"(__float_as_uint(hi)));
    return r;
}
__device__ __forceinline__ void upk2(unsigned long long d, float& lo, float& hi) {
    unsigned int a, b;
    asm("mov.b64 {%0, %1}, %2;" : "=r"(a), "=r"(b) : "l"(d));
    lo = __uint_as_float(a); hi = __uint_as_float(b);
}
__device__ __forceinline__ unsigned long long ffma2(unsigned long long a, unsigned long long b,
                                                    unsigned long long c) {
    unsigned long long d;
    asm("fma.rn.f32x2 %0, %1, %2, %3;" : "=l"(d) : "l"(a), "l"(b), "l"(c));
    return d;
}

// ---------------- conv1: 3->32, 3x3, pad 1, fused bias+relu+bn1 ----------------
__global__ __launch_bounds__(256) void conv1_k(
    const float* __restrict__ img, const float* __restrict__ w,
    const float* __restrict__ bias, const float* __restrict__ gg,
    const float* __restrict__ bb, const float* __restrict__ mm,
    const float* __restrict__ vv)
{
    __shared__ __align__(16) float s_in[3][18][18];
    __shared__ __align__(16) float s_w[27 * 32];
    __shared__ float s_scale[32], s_shift[32], s_bias[32];

    const int tx = threadIdx.x, ty = threadIdx.y;
    const int tid = ty * 16 + tx;

    for (int i = tid; i < 864; i += 256) {
        int o = i / 27, r = i % 27;
        s_w[r * 32 + o] = w[i];
    }
    if (tid < 32) {
        float sc = gg[tid] * rsqrtf(vv[tid] + 1e-5f);
        s_scale[tid] = sc;
        s_shift[tid] = bb[tid] - mm[tid] * sc;
        s_bias[tid]  = bias[tid];
    }
    const int bx0 = blockIdx.x * 16 - 1, by0 = blockIdx.y * 16 - 1;
    for (int i = tid; i < 3 * 324; i += 256) {
        int c = i / 324, r = i % 324, yy = r / 18, xx = r % 18;
        int gy = by0 + yy, gx = bx0 + xx;
        float val = (gy >= 0 && gy < HH && gx >= 0 && gx < WW)
                        ? img[c * HW + gy * WW + gx] : 0.f;
        s_in[c][yy][xx] = val;
    }
    __syncthreads();

    float acc[32];
    #pragma unroll
    for (int o = 0; o < 32; o++) acc[o] = s_bias[o];

    #pragma unroll 1
    for (int c = 0; c < 3; c++) {
        #pragma unroll
        for (int t = 0; t < 9; t++) {
            float vr = s_in[c][ty + t / 3][tx + t % 3];
            const float4* wp = (const float4*)&s_w[(c * 9 + t) * 32];
            #pragma unroll
            for (int q = 0; q < 8; q++) {
                float4 ww = wp[q];
                acc[4*q+0] = fmaf(vr, ww.x, acc[4*q+0]);
                acc[4*q+1] = fmaf(vr, ww.y, acc[4*q+1]);
                acc[4*q+2] = fmaf(vr, ww.z, acc[4*q+2]);
                acc[4*q+3] = fmaf(vr, ww.w, acc[4*q+3]);
            }
        }
    }

    const int y = blockIdx.y * 16 + ty, x = blockIdx.x * 16 + tx;
    #pragma unroll
    for (int o = 0; o < 32; o++) {
        float r = fmaxf(acc[o], 0.f) * s_scale[o] + s_shift[o];
        g_feat1[(size_t)o * HW + y * WW + x] = r;
    }
}

// ---------------- conv2 v3: 32->64, 3x3, pad 1, fused bias+relu+bn2 ----------------
// 2x2 pixel quad per thread, 16 output channels per block (blockIdx.z in 0..3).
// Per weight LDS.128 (8 packed channels): 8 FFMA2 -> smem pipe no longer binds.
// Tile: 32x32 pixels. acc = 8 pairs x 4 px = 32 ull = 64 regs.
__global__ __launch_bounds__(256, 2) void conv2_k(
    const float* __restrict__ w, const float* __restrict__ bias,
    const float* __restrict__ gg, const float* __restrict__ bb,
    const float* __restrict__ mm, const float* __restrict__ vv)
{
    __shared__ __align__(16) float s_in[8][34][34];
    __shared__ __align__(16) float s_w[8 * 9 * 16];
    __shared__ float s_scale[16], s_shift[16];

    const int tx = threadIdx.x, ty = threadIdx.y;
    const int tid = ty * 16 + tx;
    const int oz = blockIdx.z * 16;            // output-channel base

    if (tid < 16) {
        int o = oz + tid;
        float sc = gg[o] * rsqrtf(vv[o] + 1e-5f);
        s_scale[tid] = sc;
        s_shift[tid] = bb[o] - mm[o] * sc;
    }

    // acc[py][px][pair]  (pair k covers channels oz+2k, oz+2k+1)
    unsigned long long acc[2][2][8];
    #pragma unroll
    for (int k = 0; k < 8; k++) {
        unsigned long long b2 = pk2(bias[oz + 2*k], bias[oz + 2*k + 1]);
        acc[0][0][k] = b2; acc[0][1][k] = b2; acc[1][0][k] = b2; acc[1][1][k] = b2;
    }

    const int bx0 = blockIdx.x * 32 - 1, by0 = blockIdx.y * 32 - 1;

    #pragma unroll 1
    for (int cc = 0; cc < 4; cc++) {
        __syncthreads();
        // input chunk: channels [cc*8, cc*8+8), 34x34 halo tile
        for (int i = tid; i < 8 * 34 * 34; i += 256) {
            int ci = i / (34*34), r = i % (34*34), yy = r / 34, xx = r % 34;
            int gy = by0 + yy, gx = bx0 + xx;
            float val = (gy >= 0 && gy < HH && gx >= 0 && gx < WW)
                            ? g_feat1[(size_t)(cc * 8 + ci) * HW + gy * WW + gx] : 0.f;
            s_in[ci][yy][xx] = val;
        }
        // weight chunk: s_w[(ci*9+t)*16 + o] = w[(oz+o)*288 + cc*72 + ci*9+t]
        for (int i = tid; i < 1152; i += 256) {
            int r = i >> 4, o = i & 15;
            s_w[i] = w[(size_t)(oz + o) * 288 + cc * 72 + r];
        }
        __syncthreads();

        #pragma unroll 1
        for (int ci = 0; ci < 8; ci++) {
            // quad needs input rows 2ty..2ty+3, cols 2tx..2tx+3
            float vin[4][4];
            #pragma unroll
            for (int r = 0; r < 4; r++)
                #pragma unroll
                for (int c4 = 0; c4 < 4; c4++)
                    vin[r][c4] = s_in[ci][2 * ty + r][2 * tx + c4];
            #pragma unroll
            for (int t = 0; t < 9; t++) {
                int r = t / 3, cq = t % 3;
                unsigned long long v00 = pk2(vin[r    ][cq    ], vin[r    ][cq    ]);
                unsigned long long v01 = pk2(vin[r    ][cq + 1], vin[r    ][cq + 1]);
                unsigned long long v10 = pk2(vin[r + 1][cq    ], vin[r + 1][cq    ]);
                unsigned long long v11 = pk2(vin[r + 1][cq + 1], vin[r + 1][cq + 1]);
                const ulonglong2* wp = (const ulonglong2*)&s_w[(ci * 9 + t) * 16];
                #pragma unroll
                for (int k2 = 0; k2 < 4; k2++) {
                    ulonglong2 q = wp[k2];
                    acc[0][0][2*k2+0] = ffma2(v00, q.x, acc[0][0][2*k2+0]);
                    acc[0][0][2*k2+1] = ffma2(v00, q.y, acc[0][0][2*k2+1]);
                    acc[0][1][2*k2+0] = ffma2(v01, q.x, acc[0][1][2*k2+0]);
                    acc[0][1][2*k2+1] = ffma2(v01, q.y, acc[0][1][2*k2+1]);
                    acc[1][0][2*k2+0] = ffma2(v10, q.x, acc[1][0][2*k2+0]);
                    acc[1][0][2*k2+1] = ffma2(v10, q.y, acc[1][0][2*k2+1]);
                    acc[1][1][2*k2+0] = ffma2(v11, q.x, acc[1][1][2*k2+0]);
                    acc[1][1][2*k2+1] = ffma2(v11, q.y, acc[1][1][2*k2+1]);
                }
            }
        }
    }

    const int y0 = blockIdx.y * 32 + 2 * ty, x0 = blockIdx.x * 32 + 2 * tx;
    #pragma unroll
    for (int k = 0; k < 8; k++) {
        float s0 = s_scale[2*k], s1 = s_scale[2*k+1];
        float h0 = s_shift[2*k], h1 = s_shift[2*k+1];
        #pragma unroll
        for (int py = 0; py < 2; py++) {
            const size_t base = (size_t)(y0 + py + 1) * IP + (x0 + 1);
            float a0, a1, b0, b1;
            upk2(acc[py][0][k], a0, a1);   // px 0: channels 2k, 2k+1
            upk2(acc[py][1][k], b0, b1);   // px 1
            float* p0 = &g_integ[(size_t)(oz + 2*k)     * IPP + base];
            float* p1 = &g_integ[(size_t)(oz + 2*k + 1) * IPP + base];
            p0[0] = fmaxf(a0, 0.f) * s0 + h0;
            p0[1] = fmaxf(b0, 0.f) * s0 + h0;
            p1[0] = fmaxf(a1, 0.f) * s1 + h1;
            p1[1] = fmaxf(b1, 0.f) * s1 + h1;
        }
    }
}

// ---------------- zero integral-image borders ----------------
__global__ void zborder_k() {
    int i = blockIdx.x * 256 + threadIdx.x;
    if (i >= 64 * IP * 2) return;
    if (i < 64 * IP) {
        int c = i / IP, k = i % IP;
        g_integ[(size_t)c * IPP + k] = 0.f;              // row 0
    } else {
        i -= 64 * IP;
        int c = i / IP, k = i % IP;
        g_integ[(size_t)c * IPP + (size_t)k * IP] = 0.f; // col 0
    }
}

// ---------------- row-wise inclusive scan (x), fp32, coalesced ----------------
__global__ __launch_bounds__(256) void rowscan_k() {
    const int warp = threadIdx.x >> 5, lane = threadIdx.x & 31;
    const int row = blockIdx.x * 8 + warp;      // 0 .. 64*768-1
    const int c = row / HH, y = row % HH + 1;
    float* p = g_integ + (size_t)c * IPP + (size_t)y * IP + 1;

    float v[24];
    #pragma unroll
    for (int i = 0; i < 24; i++) v[i] = p[i * 32 + lane];

    float carry = 0.f;
    #pragma unroll
    for (int i = 0; i < 24; i++) {
        float x = v[i];
        #pragma unroll
        for (int d = 1; d < 32; d <<= 1) {
            float n = __shfl_up_sync(0xffffffffu, x, d);
            if (lane >= d) x += n;
        }
        x += carry;
        carry = __shfl_sync(0xffffffffu, x, 31);
        v[i] = x;
    }

    #pragma unroll
    for (int i = 0; i < 24; i++) p[i * 32 + lane] = v[i];
}

// ---------------- column-wise inclusive scan (y direction), fp32 ----------------
__global__ __launch_bounds__(256) void colscan_k() {
    int idx = blockIdx.x * 256 + threadIdx.x;
    if (idx >= 64 * WW) return;
    int c = idx / WW, x = idx % WW + 1;
    float* p = g_integ + (size_t)c * IPP + x;
    float s = 0.f;
    #pragma unroll 8
    for (int y = 1; y <= HH; y++) {
        s += p[(size_t)y * IP];
        p[(size_t)y * IP] = s;
    }
}

// ---------------- ROI pool (5x5 via integral image) + FC1(relu) + FC2 ----------------
__global__ __launch_bounds__(128) void roi_fc_k(
    const int* __restrict__ boxes,
    const float* __restrict__ fc1w, const float* __restrict__ fc1b,
    const float* __restrict__ fc2w, const float* __restrict__ fc2b,
    float* __restrict__ out)
{
    __shared__ float s_pool[1600];
    __shared__ float s_h1[128];
    __shared__ int sy0[5], sy1[5], sx0[5], sx1[5];

    const int b = blockIdx.x, tid = threadIdx.x;
    if (tid < 5) {
        int xmin = boxes[b*4+0], ymin = boxes[b*4+1];
        int xmax = boxes[b*4+2], ymax = boxes[b*4+3];
        int bh = ymax - ymin, bw = xmax - xmin;
        sy0[tid] = ymin + tid * bh / 5;
        sy1[tid] = ymin + ((tid + 1) * bh + 4) / 5;
        sx0[tid] = xmin + tid * bw / 5;
        sx1[tid] = xmin + ((tid + 1) * bw + 4) / 5;
    }
    __syncthreads();

    for (int idx = tid; idx < 1600; idx += 128) {
        int c = idx / 25, r = idx % 25, i = r / 5, j = r % 5;
        const float* I = g_integ + (size_t)c * IPP;
        double s = (double)I[(size_t)sy1[i] * IP + sx1[j]] - (double)I[(size_t)sy0[i] * IP + sx1[j]]
                 - (double)I[(size_t)sy1[i] * IP + sx0[j]] + (double)I[(size_t)sy0[i] * IP + sx0[j]];
        double area = (double)((sy1[i] - sy0[i]) * (sx1[j] - sx0[j]));
        s_pool[idx] = (float)(s / area);
    }
    __syncthreads();

    const int warp = tid >> 5, lane = tid & 31;
    for (int o = warp; o < 128; o += 4) {
        const float* wr = fc1w + o * 1600;
        float sum = 0.f;
        for (int k = lane; k < 1600; k += 32) sum = fmaf(wr[k], s_pool[k], sum);
        #pragma unroll
        for (int d = 16; d; d >>= 1) sum += __shfl_down_sync(0xffffffffu, sum, d);
        if (lane == 0) s_h1[o] = fmaxf(sum + fc1b[o], 0.f);
    }
    __syncthreads();

    {
        int o = warp;
        float sum = 0.f;
        #pragma unroll
        for (int k = lane; k < 128; k += 32) sum = fmaf(fc2w[o * 128 + k], s_h1[k], sum);
        #pragma unroll
        for (int d = 16; d; d >>= 1) sum += __shfl_down_sync(0xffffffffu, sum, d);
        if (lane == 0) out[b * 4 + o] = sum + fc2b[o];
    }
}

// ---------------- launch ----------------
extern "C" void kernel_launch(void* const* d_in, const int* in_sizes, int n_in,
                              void* d_out, int out_size)
{
    const float* image = (const float*)d_in[0];
    const int*   boxes = (const int*)  d_in[1];
    const float* c1w = (const float*)d_in[2];
    const float* c1b = (const float*)d_in[3];
    const float* b1g = (const float*)d_in[4];
    const float* b1b = (const float*)d_in[5];
    const float* b1m = (const float*)d_in[6];
    const float* b1v = (const float*)d_in[7];
    const float* c2w = (const float*)d_in[8];
    const float* c2b = (const float*)d_in[9];
    const float* b2g = (const float*)d_in[10];
    const float* b2b = (const float*)d_in[11];
    const float* b2m = (const float*)d_in[12];
    const float* b2v = (const float*)d_in[13];
    const float* f1w = (const float*)d_in[14];
    const float* f1b = (const float*)d_in[15];
    const float* f2w = (const float*)d_in[16];
    const float* f2b = (const float*)d_in[17];
    float* out = (float*)d_out;

    conv1_k<<<dim3(48, 48), dim3(16, 16)>>>(image, c1w, c1b, b1g, b1b, b1m, b1v);
    zborder_k<<<(64 * IP * 2 + 255) / 256, 256>>>();
    conv2_k<<<dim3(24, 24, 4), dim3(16, 16)>>>(c2w, c2b, b2g, b2b, b2m, b2v);
    rowscan_k<<<64 * HH / 8, 256>>>();
    colscan_k<<<(64 * WW + 255) / 256, 256>>>();
    roi_fc_k<<<512, 128>>>(boxes, f1w, f1b, f2w, f2b, out);
}